// round 1
// baseline (speedup 1.0000x reference)
#include <cuda_runtime.h>
#include <stdint.h>
#include <math.h>

#define Nn 50000
#define Ee 800000
#define Gg 16
#define Dd 64
#define Hh 128

// Scratch (allocation-free: __device__ globals)
__device__ float g_agg[Nn * Dd];    // attention-weighted edge aggregate per node
__device__ float g_nagg[Gg * Dd];   // node aggregate per graph
__device__ float g_eagg[Gg * Dd];   // edge aggregate per graph

// ---------------------------------------------------------------------------
// Packed fp32x2 helpers (sm_100+ FFMA2: 2x fp32 FMA throughput vs 3-reg FFMA)
// ---------------------------------------------------------------------------
__device__ __forceinline__ void fma2(uint64_t& d, uint64_t a, uint64_t b) {
    asm("fma.rn.f32x2 %0, %1, %2, %0;" : "+l"(d) : "l"(a), "l"(b));
}
__device__ __forceinline__ uint64_t rep2(float x) {
    uint64_t r; asm("mov.b64 %0, {%1, %1};" : "=l"(r) : "f"(x)); return r;
}
__device__ __forceinline__ float2 unpack2(uint64_t v) {
    float2 r; asm("mov.b64 {%0, %1}, %2;" : "=f"(r.x), "=f"(r.y) : "l"(v)); return r;
}
__device__ __forceinline__ void red4(float* p, float a, float b, float c, float d) {
    asm volatile("red.global.add.v4.f32 [%0], {%1,%2,%3,%4};"
                 :: "l"(p), "f"(a), "f"(b), "f"(c), "f"(d) : "memory");
}

// ---------------------------------------------------------------------------
// GEMM1: H[64,128] = relu(A[64,KTOT] @ W[KTOT,128] + b). A stored K-major
// (A[k][m]) in smem; W streamed in 64-row K-tiles through sW. H written
// K-major (Hs[h][m]) for the follow-up GEMM2. 256 threads: 4 rows x 8 cols.
// ---------------------------------------------------------------------------
template<int KTOT>
__device__ __forceinline__ void gemm_h(const float (*__restrict__ A)[64],
                                       const float* __restrict__ Wg,
                                       const float* __restrict__ b1,
                                       float (*__restrict__ Hs)[64],
                                       float* __restrict__ sW, int t)
{
    const int tx = t & 15, ty = t >> 4;
    uint64_t acc[4][4];
#pragma unroll
    for (int i = 0; i < 4; i++)
#pragma unroll
        for (int j = 0; j < 4; j++) acc[i][j] = 0ull;

    for (int kt = 0; kt < KTOT; kt += 64) {
        // stage W tile [64][128]  (2048 float4s / 256 threads = 8 each)
#pragma unroll
        for (int i = 0; i < 8; i++) {
            int idx = t + i * 256;
            int r = idx >> 5, c4 = (idx & 31) << 2;
            *(float4*)&sW[r * 128 + c4] = *(const float4*)&Wg[(size_t)(kt + r) * 128 + c4];
        }
        __syncthreads();
#pragma unroll 8
        for (int kk = 0; kk < 64; kk++) {
            float4 a = *(const float4*)&A[kt + kk][ty * 4];
            ulonglong2 w01 = *(const ulonglong2*)&sW[kk * 128 + tx * 8];
            ulonglong2 w23 = *(const ulonglong2*)&sW[kk * 128 + tx * 8 + 4];
            uint64_t a0 = rep2(a.x), a1 = rep2(a.y), a2 = rep2(a.z), a3 = rep2(a.w);
            fma2(acc[0][0], a0, w01.x); fma2(acc[0][1], a0, w01.y);
            fma2(acc[0][2], a0, w23.x); fma2(acc[0][3], a0, w23.y);
            fma2(acc[1][0], a1, w01.x); fma2(acc[1][1], a1, w01.y);
            fma2(acc[1][2], a1, w23.x); fma2(acc[1][3], a1, w23.y);
            fma2(acc[2][0], a2, w01.x); fma2(acc[2][1], a2, w01.y);
            fma2(acc[2][2], a2, w23.x); fma2(acc[2][3], a2, w23.y);
            fma2(acc[3][0], a3, w01.x); fma2(acc[3][1], a3, w01.y);
            fma2(acc[3][2], a3, w23.x); fma2(acc[3][3], a3, w23.y);
        }
        __syncthreads();
    }
    // bias + relu + transpose-store into Hs[h][m]
#pragma unroll
    for (int i = 0; i < 4; i++)
#pragma unroll
        for (int p = 0; p < 4; p++) {
            float2 v = unpack2(acc[i][p]);
            float2 b = *(const float2*)&b1[tx * 8 + p * 2];
            Hs[tx * 8 + p * 2][ty * 4 + i]     = fmaxf(v.x + b.x, 0.f);
            Hs[tx * 8 + p * 2 + 1][ty * 4 + i] = fmaxf(v.y + b.y, 0.f);
        }
    __syncthreads();
}

// ---------------------------------------------------------------------------
// GEMM2: O[64,64] = Hs^T[64,128] @ W2[128,64] + b2. 256 threads: 4 rows x 4 cols.
// ---------------------------------------------------------------------------
__device__ __forceinline__ void gemm_o(const float (*__restrict__ Hs)[64],
                                       const float* __restrict__ Wg,
                                       const float* __restrict__ b2,
                                       float* __restrict__ sW, int t,
                                       float o[4][4])
{
    const int tx = t & 15, ty = t >> 4;
    uint64_t acc[4][2];
#pragma unroll
    for (int i = 0; i < 4; i++) { acc[i][0] = 0ull; acc[i][1] = 0ull; }

    // stage W2 [128][64]
#pragma unroll
    for (int i = 0; i < 8; i++) {
        int idx = t + i * 256;
        int r = idx >> 4, c4 = (idx & 15) << 2;
        *(float4*)&sW[r * 64 + c4] = *(const float4*)&Wg[(size_t)r * 64 + c4];
    }
    __syncthreads();
#pragma unroll 8
    for (int kk = 0; kk < 128; kk++) {
        float4 a = *(const float4*)&Hs[kk][ty * 4];
        ulonglong2 w = *(const ulonglong2*)&sW[kk * 64 + tx * 4];
        uint64_t a0 = rep2(a.x), a1 = rep2(a.y), a2 = rep2(a.z), a3 = rep2(a.w);
        fma2(acc[0][0], a0, w.x); fma2(acc[0][1], a0, w.y);
        fma2(acc[1][0], a1, w.x); fma2(acc[1][1], a1, w.y);
        fma2(acc[2][0], a2, w.x); fma2(acc[2][1], a2, w.y);
        fma2(acc[3][0], a3, w.x); fma2(acc[3][1], a3, w.y);
    }
    __syncthreads();
#pragma unroll
    for (int i = 0; i < 4; i++)
#pragma unroll
        for (int p = 0; p < 2; p++) {
            float2 v = unpack2(acc[i][p]);
            float2 b = *(const float2*)&b2[tx * 4 + p * 2];
            o[i][p * 2]     = v.x + b.x;
            o[i][p * 2 + 1] = v.y + b.y;
        }
}

// ---------------------------------------------------------------------------
// Edge kernel: fused edge MLP + attention MLP + scatter
// ---------------------------------------------------------------------------
struct SmemE {
    float A[256][64];       // gathered input, K-major
    float W[64 * 128];      // streamed weight tile (also used as [128][64])
    float Hs[128][64];      // hidden, K-major
    float eagg[16 * 64];    // per-block partial edge aggregate per graph
    int srcs[64], dsts[64], gidx[64];
};

__global__ void __launch_bounds__(256, 1)
edge_kernel(const float* __restrict__ x, const int* __restrict__ ei,
            const float* __restrict__ e, const float* __restrict__ u,
            const int* __restrict__ batch,
            const float* __restrict__ We1, const float* __restrict__ be1,
            const float* __restrict__ We2, const float* __restrict__ be2,
            const float* __restrict__ Wa1, const float* __restrict__ ba1,
            const float* __restrict__ Wa2, const float* __restrict__ ba2,
            float* __restrict__ e_out)
{
    extern __shared__ char smem_raw[];
    SmemE& s = *reinterpret_cast<SmemE*>(smem_raw);
    const int t = threadIdx.x;
    const int eb = blockIdx.x * 64;

    if (t < 64) {
        int src = ei[eb + t];
        int dst = ei[Ee + eb + t];
        s.srcs[t] = src; s.dsts[t] = dst; s.gidx[t] = batch[src];
    }
#pragma unroll
    for (int i = 0; i < 4; i++) s.eagg[t + i * 256] = 0.f;
    __syncthreads();

    // Build A = [xs | xd | e | u_src], K-major
    for (int i = t; i < 1024; i += 256) {
        int m = i >> 4, k4 = (i & 15) << 2;
        int src = s.srcs[m], dst = s.dsts[m], g = s.gidx[m];
        float4 v;
        v = *(const float4*)&x[(size_t)src * 64 + k4];
        s.A[k4][m] = v.x; s.A[k4 + 1][m] = v.y; s.A[k4 + 2][m] = v.z; s.A[k4 + 3][m] = v.w;
        v = *(const float4*)&x[(size_t)dst * 64 + k4];
        s.A[64 + k4][m] = v.x; s.A[64 + k4 + 1][m] = v.y; s.A[64 + k4 + 2][m] = v.z; s.A[64 + k4 + 3][m] = v.w;
        v = *(const float4*)&e[(size_t)(eb + m) * 64 + k4];
        s.A[128 + k4][m] = v.x; s.A[128 + k4 + 1][m] = v.y; s.A[128 + k4 + 2][m] = v.z; s.A[128 + k4 + 3][m] = v.w;
        v = *(const float4*)&u[g * 64 + k4];
        s.A[192 + k4][m] = v.x; s.A[192 + k4 + 1][m] = v.y; s.A[192 + k4 + 2][m] = v.z; s.A[192 + k4 + 3][m] = v.w;
    }
    __syncthreads();

    const int tx = t & 15, ty = t >> 4;

    // e_new = MLP_e(A)
    gemm_h<256>(s.A, We1, be1, s.Hs, s.W, t);
    float enew[4][4];
    gemm_o(s.Hs, We2, be2, s.W, t, enew);

    // write e_new out; splice into A rows [128,192); accumulate per-graph sums
#pragma unroll
    for (int i = 0; i < 4; i++) {
        int row = ty * 4 + i;
        *(float4*)&e_out[(size_t)(eb + row) * 64 + tx * 4] =
            make_float4(enew[i][0], enew[i][1], enew[i][2], enew[i][3]);
        int g = s.gidx[row];
#pragma unroll
        for (int j = 0; j < 4; j++) {
            s.A[128 + tx * 4 + j][row] = enew[i][j];
            atomicAdd(&s.eagg[g * 64 + tx * 4 + j], enew[i][j]);
        }
    }
    __syncthreads();

    // a = sigmoid(MLP_a(A with e_new))
    gemm_h<256>(s.A, Wa1, ba1, s.Hs, s.W, t);
    float av[4][4];
    gemm_o(s.Hs, Wa2, ba2, s.W, t, av);

    // scatter e_new * a into g_agg[dst]
#pragma unroll
    for (int i = 0; i < 4; i++) {
        int row = ty * 4 + i;
        int dst = s.dsts[row];
        float w0 = enew[i][0] / (1.f + __expf(-av[i][0]));
        float w1 = enew[i][1] / (1.f + __expf(-av[i][1]));
        float w2 = enew[i][2] / (1.f + __expf(-av[i][2]));
        float w3 = enew[i][3] / (1.f + __expf(-av[i][3]));
        red4(&g_agg[(size_t)dst * 64 + tx * 4], w0, w1, w2, w3);
    }

    // flush per-block edge aggregate (256 v4 reds per block)
    {
        int g = t >> 4, c4 = (t & 15) << 2;
        const float* p = &s.eagg[g * 64 + c4];
        red4(&g_eagg[g * 64 + c4], p[0], p[1], p[2], p[3]);
    }
}

// ---------------------------------------------------------------------------
// Node kernel: x_new = MLP_n([x | agg | u[batch]]), plus per-graph node agg
// ---------------------------------------------------------------------------
struct SmemN {
    float A[192][64];
    float W[64 * 128];
    float Hs[128][64];
    float nagg[16 * 64];
    int gid[64];
};

__global__ void __launch_bounds__(256, 1)
node_kernel(const float* __restrict__ x, const float* __restrict__ u,
            const int* __restrict__ batch,
            const float* __restrict__ Wn1, const float* __restrict__ bn1,
            const float* __restrict__ Wn2, const float* __restrict__ bn2,
            float* __restrict__ x_out)
{
    extern __shared__ char smem_raw[];
    SmemN& s = *reinterpret_cast<SmemN*>(smem_raw);
    const int t = threadIdx.x;
    const int nb = blockIdx.x * 64;

    if (t < 64) {
        int r = nb + t; if (r >= Nn) r = Nn - 1;
        s.gid[t] = batch[r];
    }
#pragma unroll
    for (int i = 0; i < 4; i++) s.nagg[t + i * 256] = 0.f;
    __syncthreads();

    for (int i = t; i < 1024; i += 256) {
        int m = i >> 4, k4 = (i & 15) << 2;
        int r = nb + m; if (r >= Nn) r = Nn - 1;
        float4 v;
        v = *(const float4*)&x[(size_t)r * 64 + k4];
        s.A[k4][m] = v.x; s.A[k4 + 1][m] = v.y; s.A[k4 + 2][m] = v.z; s.A[k4 + 3][m] = v.w;
        v = *(const float4*)&g_agg[(size_t)r * 64 + k4];
        s.A[64 + k4][m] = v.x; s.A[64 + k4 + 1][m] = v.y; s.A[64 + k4 + 2][m] = v.z; s.A[64 + k4 + 3][m] = v.w;
        v = *(const float4*)&u[s.gid[m] * 64 + k4];
        s.A[128 + k4][m] = v.x; s.A[128 + k4 + 1][m] = v.y; s.A[128 + k4 + 2][m] = v.z; s.A[128 + k4 + 3][m] = v.w;
    }
    __syncthreads();

    gemm_h<192>(s.A, Wn1, bn1, s.Hs, s.W, t);
    float xo[4][4];
    gemm_o(s.Hs, Wn2, bn2, s.W, t, xo);

    const int tx = t & 15, ty = t >> 4;
#pragma unroll
    for (int i = 0; i < 4; i++) {
        int row = ty * 4 + i;
        int r = nb + row;
        if (r < Nn) {
            *(float4*)&x_out[(size_t)r * 64 + tx * 4] =
                make_float4(xo[i][0], xo[i][1], xo[i][2], xo[i][3]);
            int g = s.gid[row];
#pragma unroll
            for (int j = 0; j < 4; j++)
                atomicAdd(&s.nagg[g * 64 + tx * 4 + j], xo[i][j]);
        }
    }
    __syncthreads();
    {
        int g = t >> 4, c4 = (t & 15) << 2;
        const float* p = &s.nagg[g * 64 + c4];
        red4(&g_nagg[g * 64 + c4], p[0], p[1], p[2], p[3]);
    }
}

// ---------------------------------------------------------------------------
// Global kernel: u_new = MLP_g([u | node_agg | edge_agg]), G=16 rows (tiny)
// ---------------------------------------------------------------------------
__global__ void __launch_bounds__(256)
global_kernel(const float* __restrict__ u,
              const float* __restrict__ Wg1, const float* __restrict__ bg1,
              const float* __restrict__ Wg2, const float* __restrict__ bg2,
              float* __restrict__ u_out)
{
    __shared__ float in[16][192];
    __shared__ float hid[16][128];
    const int t = threadIdx.x;
    for (int i = t; i < 16 * 64; i += 256) {
        int g = i >> 6, k = i & 63;
        in[g][k] = u[i];
        in[g][64 + k] = g_nagg[i];
        in[g][128 + k] = g_eagg[i];
    }
    __syncthreads();
    for (int i = t; i < 16 * 128; i += 256) {
        int g = i >> 7, h = i & 127;
        float acc = bg1[h];
        for (int k = 0; k < 192; k++) acc += in[g][k] * Wg1[(size_t)k * 128 + h];
        hid[g][h] = fmaxf(acc, 0.f);
    }
    __syncthreads();
    for (int i = t; i < 16 * 64; i += 256) {
        int g = i >> 6, c = i & 63;
        float acc = bg2[c];
        for (int k = 0; k < 128; k++) acc += hid[g][k] * Wg2[(size_t)k * 64 + c];
        u_out[i] = acc;
    }
}

__global__ void zero_kernel()
{
    size_t idx = (size_t)blockIdx.x * 256 + threadIdx.x;
    float4 z = make_float4(0.f, 0.f, 0.f, 0.f);
    if (idx < (size_t)Nn * Dd / 4) ((float4*)g_agg)[idx] = z;
    if (idx < 256) {
        ((float4*)g_nagg)[idx] = z;
        ((float4*)g_eagg)[idx] = z;
    }
}

extern "C" void kernel_launch(void* const* d_in, const int* in_sizes, int n_in,
                              void* d_out, int out_size)
{
    const float* x     = (const float*)d_in[0];
    const int*   ei    = (const int*)d_in[1];
    const float* e     = (const float*)d_in[2];
    const float* u     = (const float*)d_in[3];
    const int*   batch = (const int*)d_in[4];
    const float* We1 = (const float*)d_in[5];
    const float* be1 = (const float*)d_in[6];
    const float* We2 = (const float*)d_in[7];
    const float* be2 = (const float*)d_in[8];
    const float* Wa1 = (const float*)d_in[9];
    const float* ba1 = (const float*)d_in[10];
    const float* Wa2 = (const float*)d_in[11];
    const float* ba2 = (const float*)d_in[12];
    const float* Wn1 = (const float*)d_in[13];
    const float* bn1 = (const float*)d_in[14];
    const float* Wn2 = (const float*)d_in[15];
    const float* bn2 = (const float*)d_in[16];
    const float* Wg1 = (const float*)d_in[17];
    const float* bg1 = (const float*)d_in[18];
    const float* Wg2 = (const float*)d_in[19];
    const float* bg2 = (const float*)d_in[20];

    float* out   = (float*)d_out;
    float* x_out = out;
    float* e_out = out + (size_t)Nn * Dd;
    float* u_out = out + (size_t)Nn * Dd + (size_t)Ee * Dd;

    cudaFuncSetAttribute(edge_kernel, cudaFuncAttributeMaxDynamicSharedMemorySize, (int)sizeof(SmemE));
    cudaFuncSetAttribute(node_kernel, cudaFuncAttributeMaxDynamicSharedMemorySize, (int)sizeof(SmemN));

    zero_kernel<<<3125, 256>>>();
    edge_kernel<<<Ee / 64, 256, sizeof(SmemE)>>>(x, ei, e, u, batch,
                                                 We1, be1, We2, be2,
                                                 Wa1, ba1, Wa2, ba2, e_out);
    node_kernel<<<(Nn + 63) / 64, 256, sizeof(SmemN)>>>(x, u, batch,
                                                        Wn1, bn1, Wn2, bn2, x_out);
    global_kernel<<<1, 256>>>(u, Wg1, bg1, Wg2, bg2, u_out);
}

// round 3
// speedup vs baseline: 1.5505x; 1.5505x over previous
#include <cuda_runtime.h>
#include <stdint.h>
#include <math.h>

#define Nn 50000
#define Ee 800000
#define Gg 16
#define Dd 64
#define Hh 128

// Scratch (allocation-free: __device__ globals)
__device__ float g_agg[Nn * Dd];     // attention-weighted edge aggregate per node
__device__ float g_nagg[Gg * Dd];    // node aggregate per graph
__device__ float g_eagg[Gg * Dd];    // edge aggregate per graph
__device__ float g_U1e[Gg * Hh];     // be1 + u @ We1[192:256]
__device__ float g_U1a[Gg * Hh];     // ba1 + u @ Wa1[192:256]
__device__ float g_U1n[Gg * Hh];     // bn1 + u @ Wn1[128:192]

// ---------------------------------------------------------------------------
// Packed fp32x2 helpers (sm_100+ FFMA2: 2x fp32 FMA throughput)
// ---------------------------------------------------------------------------
__device__ __forceinline__ void fma2(uint64_t& d, uint64_t a, uint64_t b) {
    asm("fma.rn.f32x2 %0, %1, %2, %0;" : "+l"(d) : "l"(a), "l"(b));
}
__device__ __forceinline__ uint64_t rep2(float x) {
    uint64_t r; asm("mov.b64 %0, {%1, %1};" : "=l"(r) : "f"(x)); return r;
}
__device__ __forceinline__ float2 unpack2(uint64_t v) {
    float2 r; asm("mov.b64 {%0, %1}, %2;" : "=f"(r.x), "=f"(r.y) : "l"(v)); return r;
}
__device__ __forceinline__ void red4(float* p, float a, float b, float c, float d) {
    asm volatile("red.global.add.v4.f32 [%0], {%1,%2,%3,%4};"
                 :: "l"(p), "f"(a), "f"(b), "f"(c), "f"(d) : "memory");
}
// cp.async helpers
__device__ __forceinline__ void cp16(float* smem_dst, const float* gsrc) {
    uint32_t s = (uint32_t)__cvta_generic_to_shared(smem_dst);
    asm volatile("cp.async.cg.shared.global [%0], [%1], 16;" :: "r"(s), "l"(gsrc));
}
__device__ __forceinline__ void cp_commit() { asm volatile("cp.async.commit_group;"); }
template<int N> __device__ __forceinline__ void cp_wait() {
    asm volatile("cp.async.wait_group %0;" :: "n"(N));
}

// ---------------------------------------------------------------------------
// W staging (cp.async): GEMM1 tile = 32 rows x 128 cols (16KB),
//                       GEMM2 tile = 64 rows x 64 cols  (16KB)
// ---------------------------------------------------------------------------
__device__ __forceinline__ void stage_w1(const float* __restrict__ Wg, int kt,
                                         float* __restrict__ dst, int t) {
    const float* src = Wg + (size_t)kt * 32 * 128;
#pragma unroll
    for (int i = 0; i < 4; i++) {
        int idx = t + i * 256;
        int r = idx >> 5, c4 = (idx & 31) << 2;
        cp16(dst + r * 128 + c4, src + r * 128 + c4);
    }
}
__device__ __forceinline__ void stage_w2(const float* __restrict__ Wg, int kt,
                                         float* __restrict__ dst, int t) {
    const float* src = Wg + (size_t)kt * 64 * 64;
#pragma unroll
    for (int i = 0; i < 4; i++) {
        int idx = t + i * 256;
        int r = idx >> 4, c4 = (idx & 15) << 2;
        cp16(dst + r * 64 + c4, src + r * 64 + c4);
    }
}

// ---------------------------------------------------------------------------
// GEMM1: Hs[128][64] = relu(A^T @ W1 + U1[g]) ; A is K-major, xor-swizzled.
// acc initialized from per-graph precomputed U1 (bias folded in).
// ---------------------------------------------------------------------------
template<int KTOT>
__device__ __forceinline__ void gemm_h(const float* __restrict__ A,
                                       const float* __restrict__ Wg,
                                       const float* __restrict__ U1,
                                       const int* __restrict__ gidx,
                                       float* __restrict__ Hs,
                                       float* __restrict__ sW, int t)
{
    const int tx = t & 15, ty = t >> 4;
    uint64_t acc[4][4];
#pragma unroll
    for (int i = 0; i < 4; i++) {
        int g = gidx[ty * 4 + i];
        const float* up = U1 + g * 128 + tx * 8;
#pragma unroll
        for (int p = 0; p < 4; p++) acc[i][p] = *(const uint64_t*)(up + p * 2);
    }
    constexpr int NT = KTOT / 32;
    stage_w1(Wg, 0, sW, t);
    cp_commit();
#pragma unroll
    for (int kt = 0; kt < NT; kt++) {
        if (kt + 1 < NT) {
            stage_w1(Wg, kt + 1, sW + ((kt + 1) & 1) * 4096, t);
            cp_commit();
            cp_wait<1>();
        } else cp_wait<0>();
        __syncthreads();
        const float* W = sW + (kt & 1) * 4096;
#pragma unroll
        for (int kk = 0; kk < 32; kk++) {
            int k = kt * 32 + kk;
            float4 a = *(const float4*)(A + k * 64 + ((ty ^ ((k >> 2) & 15)) << 2));
            ulonglong2 w01 = *(const ulonglong2*)(W + kk * 128 + tx * 8);
            ulonglong2 w23 = *(const ulonglong2*)(W + kk * 128 + tx * 8 + 4);
            uint64_t a0 = rep2(a.x), a1 = rep2(a.y), a2 = rep2(a.z), a3 = rep2(a.w);
            fma2(acc[0][0], a0, w01.x); fma2(acc[0][1], a0, w01.y);
            fma2(acc[0][2], a0, w23.x); fma2(acc[0][3], a0, w23.y);
            fma2(acc[1][0], a1, w01.x); fma2(acc[1][1], a1, w01.y);
            fma2(acc[1][2], a1, w23.x); fma2(acc[1][3], a1, w23.y);
            fma2(acc[2][0], a2, w01.x); fma2(acc[2][1], a2, w01.y);
            fma2(acc[2][2], a2, w23.x); fma2(acc[2][3], a2, w23.y);
            fma2(acc[3][0], a3, w01.x); fma2(acc[3][1], a3, w01.y);
            fma2(acc[3][2], a3, w23.x); fma2(acc[3][3], a3, w23.y);
        }
        __syncthreads();
    }
    // relu + swizzled transpose store into Hs (bias already in U1)
#pragma unroll
    for (int i = 0; i < 4; i++)
#pragma unroll
        for (int p = 0; p < 4; p++) {
            float2 v = unpack2(acc[i][p]);
            int h0 = tx * 8 + p * 2;
            int c = ((ty ^ ((h0 >> 2) & 15)) << 2) | i;
            Hs[h0 * 64 + c]       = fmaxf(v.x, 0.f);
            Hs[(h0 + 1) * 64 + c] = fmaxf(v.y, 0.f);
        }
    __syncthreads();
}

// ---------------------------------------------------------------------------
// GEMM2: O[64,64] = Hs^T @ W2 + b2 ; Hs K-major xor-swizzled.
// ---------------------------------------------------------------------------
__device__ __forceinline__ void gemm_o(const float* __restrict__ Hs,
                                       const float* __restrict__ Wg,
                                       const float* __restrict__ b2,
                                       float* __restrict__ sW, int t,
                                       float o[4][4])
{
    const int tx = t & 15, ty = t >> 4;
    uint64_t b0 = *(const uint64_t*)(b2 + tx * 4);
    uint64_t b1 = *(const uint64_t*)(b2 + tx * 4 + 2);
    uint64_t acc[4][2];
#pragma unroll
    for (int i = 0; i < 4; i++) { acc[i][0] = b0; acc[i][1] = b1; }
    stage_w2(Wg, 0, sW, t);
    cp_commit();
#pragma unroll
    for (int kt = 0; kt < 2; kt++) {
        if (kt == 0) { stage_w2(Wg, 1, sW + 4096, t); cp_commit(); cp_wait<1>(); }
        else cp_wait<0>();
        __syncthreads();
        const float* W = sW + kt * 4096;
#pragma unroll 8
        for (int kk = 0; kk < 64; kk++) {
            int k = kt * 64 + kk;
            float4 a = *(const float4*)(Hs + k * 64 + ((ty ^ ((k >> 2) & 15)) << 2));
            ulonglong2 w = *(const ulonglong2*)(W + kk * 64 + tx * 4);
            uint64_t a0 = rep2(a.x), a1 = rep2(a.y), a2 = rep2(a.z), a3 = rep2(a.w);
            fma2(acc[0][0], a0, w.x); fma2(acc[0][1], a0, w.y);
            fma2(acc[1][0], a1, w.x); fma2(acc[1][1], a1, w.y);
            fma2(acc[2][0], a2, w.x); fma2(acc[2][1], a2, w.y);
            fma2(acc[3][0], a3, w.x); fma2(acc[3][1], a3, w.y);
        }
        __syncthreads();
    }
#pragma unroll
    for (int i = 0; i < 4; i++)
#pragma unroll
        for (int p = 0; p < 2; p++) {
            float2 v = unpack2(acc[i][p]);
            o[i][p * 2]     = v.x;
            o[i][p * 2 + 1] = v.y;
        }
}

// ---------------------------------------------------------------------------
// Edge kernel: fused edge MLP + attention MLP + scatter. 2 CTAs/SM.
// smem: A[192*64] | sW[2*4096] | Hs[128*64] | srcs/dsts/gidx  = 112.75 KB
// ---------------------------------------------------------------------------
#define SME_A  0
#define SME_W  12288
#define SME_H  20480
#define SME_IX 28672
#define SME_FLOATS (28672 + 192)

__global__ void __launch_bounds__(256, 2)
edge_kernel(const float* __restrict__ x, const int* __restrict__ ei,
            const float* __restrict__ e, const int* __restrict__ batch,
            const float* __restrict__ We1, const float* __restrict__ We2,
            const float* __restrict__ be2,
            const float* __restrict__ Wa1, const float* __restrict__ Wa2,
            const float* __restrict__ ba2,
            float* __restrict__ e_out)
{
    extern __shared__ float smem[];
    float* A  = smem + SME_A;
    float* sW = smem + SME_W;
    float* Hs = smem + SME_H;
    int* srcs = (int*)(smem + SME_IX);
    int* dsts = srcs + 64;
    int* gidx = dsts + 64;
    const int t = threadIdx.x;
    const int eb = blockIdx.x * 64;

    if (t < 64) {
        int s_ = ei[eb + t], d_ = ei[Ee + eb + t];
        srcs[t] = s_; dsts[t] = d_; gidx[t] = batch[s_];
    }
    __syncthreads();

    // Build A = [xs | xd | e], K-major, xor-swizzled (2-way conflict stores)
    for (int i = t; i < 1024; i += 256) {
        int m = i >> 4, k4 = (i & 15) << 2;
        int c = (((m >> 2) ^ (k4 >> 2)) << 2) | (m & 3);
        float4 v;
        v = *(const float4*)&x[(size_t)srcs[m] * 64 + k4];
        A[k4 * 64 + c] = v.x; A[(k4 + 1) * 64 + c] = v.y;
        A[(k4 + 2) * 64 + c] = v.z; A[(k4 + 3) * 64 + c] = v.w;
        v = *(const float4*)&x[(size_t)dsts[m] * 64 + k4];
        A[(64 + k4) * 64 + c] = v.x; A[(64 + k4 + 1) * 64 + c] = v.y;
        A[(64 + k4 + 2) * 64 + c] = v.z; A[(64 + k4 + 3) * 64 + c] = v.w;
        v = *(const float4*)&e[(size_t)(eb + m) * 64 + k4];
        A[(128 + k4) * 64 + c] = v.x; A[(128 + k4 + 1) * 64 + c] = v.y;
        A[(128 + k4 + 2) * 64 + c] = v.z; A[(128 + k4 + 3) * 64 + c] = v.w;
    }
    __syncthreads();

    const int tx = t & 15, ty = t >> 4;

    // e_new = MLP_e(A)
    gemm_h<192>(A, We1, g_U1e, gidx, Hs, sW, t);
    float enew[4][4];
    gemm_o(Hs, We2, be2, sW, t, enew);
    __syncthreads();                 // all Hs reads done; reuse Hs as eagg

    float* eagg = Hs;                // 16*64 floats overlay
#pragma unroll
    for (int i = 0; i < 4; i++) eagg[t + i * 256] = 0.f;
    __syncthreads();

    // write e_new; splice into A rows [128,192); accumulate per-graph sums
#pragma unroll
    for (int i = 0; i < 4; i++) {
        int row = ty * 4 + i;
        *(float4*)&e_out[(size_t)(eb + row) * 64 + tx * 4] =
            make_float4(enew[i][0], enew[i][1], enew[i][2], enew[i][3]);
        int cA = ((ty ^ tx) << 2) | i;
        int g = gidx[row];
#pragma unroll
        for (int j = 0; j < 4; j++) {
            A[(128 + tx * 4 + j) * 64 + cA] = enew[i][j];
            atomicAdd(&eagg[g * 64 + tx * 4 + j], enew[i][j]);
        }
    }
    __syncthreads();
    {
        int g = t >> 4, c4 = (t & 15) << 2;
        const float* p = &eagg[g * 64 + c4];
        red4(&g_eagg[g * 64 + c4], p[0], p[1], p[2], p[3]);
    }

    // a = sigmoid(MLP_a(A with e_new))
    gemm_h<192>(A, Wa1, g_U1a, gidx, Hs, sW, t);
    float av[4][4];
    gemm_o(Hs, Wa2, ba2, sW, t, av);

    // scatter e_new * a into g_agg[dst]
#pragma unroll
    for (int i = 0; i < 4; i++) {
        int row = ty * 4 + i;
        int dst = dsts[row];
        float w0 = enew[i][0] / (1.f + __expf(-av[i][0]));
        float w1 = enew[i][1] / (1.f + __expf(-av[i][1]));
        float w2 = enew[i][2] / (1.f + __expf(-av[i][2]));
        float w3 = enew[i][3] / (1.f + __expf(-av[i][3]));
        red4(&g_agg[(size_t)dst * 64 + tx * 4], w0, w1, w2, w3);
    }
}

// ---------------------------------------------------------------------------
// Node kernel: x_new = MLP_n([x | agg] + U1n[g]), per-graph node agg
// smem: A[128*64] | sW[2*4096] | Hs[128*64] | gid  = 96.25 KB (2 CTAs/SM)
// ---------------------------------------------------------------------------
#define SMN_A  0
#define SMN_W  8192
#define SMN_H  16384
#define SMN_IX 24576
#define SMN_FLOATS (24576 + 64)

__global__ void __launch_bounds__(256, 2)
node_kernel(const float* __restrict__ x, const int* __restrict__ batch,
            const float* __restrict__ Wn1, const float* __restrict__ Wn2,
            const float* __restrict__ bn2,
            float* __restrict__ x_out)
{
    extern __shared__ float smem[];
    float* A  = smem + SMN_A;
    float* sW = smem + SMN_W;
    float* Hs = smem + SMN_H;
    int* gid  = (int*)(smem + SMN_IX);
    const int t = threadIdx.x;
    const int nb = blockIdx.x * 64;

    if (t < 64) {
        int r = nb + t; if (r >= Nn) r = Nn - 1;
        gid[t] = batch[r];
    }
    __syncthreads();

    for (int i = t; i < 1024; i += 256) {
        int m = i >> 4, k4 = (i & 15) << 2;
        int r = nb + m; if (r >= Nn) r = Nn - 1;
        int c = (((m >> 2) ^ (k4 >> 2)) << 2) | (m & 3);
        float4 v;
        v = *(const float4*)&x[(size_t)r * 64 + k4];
        A[k4 * 64 + c] = v.x; A[(k4 + 1) * 64 + c] = v.y;
        A[(k4 + 2) * 64 + c] = v.z; A[(k4 + 3) * 64 + c] = v.w;
        v = *(const float4*)&g_agg[(size_t)r * 64 + k4];
        A[(64 + k4) * 64 + c] = v.x; A[(64 + k4 + 1) * 64 + c] = v.y;
        A[(64 + k4 + 2) * 64 + c] = v.z; A[(64 + k4 + 3) * 64 + c] = v.w;
    }
    __syncthreads();

    gemm_h<128>(A, Wn1, g_U1n, gid, Hs, sW, t);
    float xo[4][4];
    gemm_o(Hs, Wn2, bn2, sW, t, xo);
    __syncthreads();

    float* nagg = Hs;
#pragma unroll
    for (int i = 0; i < 4; i++) nagg[t + i * 256] = 0.f;
    __syncthreads();

    const int tx = t & 15, ty = t >> 4;
#pragma unroll
    for (int i = 0; i < 4; i++) {
        int row = ty * 4 + i;
        int r = nb + row;
        if (r < Nn) {
            *(float4*)&x_out[(size_t)r * 64 + tx * 4] =
                make_float4(xo[i][0], xo[i][1], xo[i][2], xo[i][3]);
            int g = gid[row];
#pragma unroll
            for (int j = 0; j < 4; j++)
                atomicAdd(&nagg[g * 64 + tx * 4 + j], xo[i][j]);
        }
    }
    __syncthreads();
    {
        int g = t >> 4, c4 = (t & 15) << 2;
        const float* p = &nagg[g * 64 + c4];
        red4(&g_nagg[g * 64 + c4], p[0], p[1], p[2], p[3]);
    }
}

// ---------------------------------------------------------------------------
// Global kernel: 16 blocks (one per graph) x 128 threads, coalesced W reads
// ---------------------------------------------------------------------------
__global__ void __launch_bounds__(128)
global_kernel(const float* __restrict__ u,
              const float* __restrict__ Wg1, const float* __restrict__ bg1,
              const float* __restrict__ Wg2, const float* __restrict__ bg2,
              float* __restrict__ u_out)
{
    __shared__ float in[192];
    __shared__ float hid[128];
    const int g = blockIdx.x, t = threadIdx.x;
    if (t < 64) {
        in[t]       = u[g * 64 + t];
        in[64 + t]  = g_nagg[g * 64 + t];
        in[128 + t] = g_eagg[g * 64 + t];
    }
    __syncthreads();
    float acc = bg1[t];
#pragma unroll 8
    for (int k = 0; k < 192; k++) acc += in[k] * Wg1[(size_t)k * 128 + t];
    hid[t] = fmaxf(acc, 0.f);
    __syncthreads();
    if (t < 64) {
        float a2 = bg2[t];
#pragma unroll 8
        for (int k = 0; k < 128; k++) a2 += hid[k] * Wg2[(size_t)k * 64 + t];
        u_out[g * 64 + t] = a2;
    }
}

// ---------------------------------------------------------------------------
// Prep kernel: zero aggregates + precompute U1 tables (bias folded)
// ---------------------------------------------------------------------------
__global__ void __launch_bounds__(256)
prep_kernel(const float* __restrict__ u,
            const float* __restrict__ We1, const float* __restrict__ be1,
            const float* __restrict__ Wa1, const float* __restrict__ ba1,
            const float* __restrict__ Wn1, const float* __restrict__ bn1)
{
    const int b = blockIdx.x, t = threadIdx.x;
    size_t idx = (size_t)b * 256 + t;
    const size_t n4 = (size_t)Nn * Dd / 4;
    float4 z = make_float4(0.f, 0.f, 0.f, 0.f);
    for (size_t i = idx; i < n4; i += (size_t)gridDim.x * 256) ((float4*)g_agg)[i] = z;
    if (idx < 256) { ((float4*)g_nagg)[idx] = z; ((float4*)g_eagg)[idx] = z; }
    if (b < 3) {
        const float* W   = (b == 0) ? We1 + 192 * 128 : (b == 1) ? Wa1 + 192 * 128 : Wn1 + 128 * 128;
        const float* bias = (b == 0) ? be1 : (b == 1) ? ba1 : bn1;
        float* out       = (b == 0) ? g_U1e : (b == 1) ? g_U1a : g_U1n;
        for (int i = t; i < Gg * Hh; i += 256) {
            int g = i >> 7, h = i & 127;
            float acc = bias[h];
#pragma unroll 8
            for (int k = 0; k < 64; k++) acc += u[g * 64 + k] * W[(size_t)k * 128 + h];
            out[i] = acc;
        }
    }
}

extern "C" void kernel_launch(void* const* d_in, const int* in_sizes, int n_in,
                              void* d_out, int out_size)
{
    const float* x     = (const float*)d_in[0];
    const int*   ei    = (const int*)d_in[1];
    const float* e     = (const float*)d_in[2];
    const float* u     = (const float*)d_in[3];
    const int*   batch = (const int*)d_in[4];
    const float* We1 = (const float*)d_in[5];
    const float* be1 = (const float*)d_in[6];
    const float* We2 = (const float*)d_in[7];
    const float* be2 = (const float*)d_in[8];
    const float* Wa1 = (const float*)d_in[9];
    const float* ba1 = (const float*)d_in[10];
    const float* Wa2 = (const float*)d_in[11];
    const float* ba2 = (const float*)d_in[12];
    const float* Wn1 = (const float*)d_in[13];
    const float* bn1 = (const float*)d_in[14];
    const float* Wn2 = (const float*)d_in[15];
    const float* bn2 = (const float*)d_in[16];
    const float* Wg1 = (const float*)d_in[17];
    const float* bg1 = (const float*)d_in[18];
    const float* Wg2 = (const float*)d_in[19];
    const float* bg2 = (const float*)d_in[20];

    float* out   = (float*)d_out;
    float* x_out = out;
    float* e_out = out + (size_t)Nn * Dd;
    float* u_out = out + (size_t)Nn * Dd + (size_t)Ee * Dd;

    static int attr_done = 0;
    if (!attr_done) {
        cudaFuncSetAttribute(edge_kernel, cudaFuncAttributeMaxDynamicSharedMemorySize,
                             SME_FLOATS * 4);
        cudaFuncSetAttribute(node_kernel, cudaFuncAttributeMaxDynamicSharedMemorySize,
                             SMN_FLOATS * 4);
        attr_done = 1;
    }

    prep_kernel<<<3125, 256>>>(u, We1, be1, Wa1, ba1, Wn1, bn1);
    edge_kernel<<<Ee / 64, 256, SME_FLOATS * 4>>>(x, ei, e, batch,
                                                  We1, We2, be2, Wa1, Wa2, ba2, e_out);
    node_kernel<<<(Nn + 63) / 64, 256, SMN_FLOATS * 4>>>(x, batch, Wn1, Wn2, bn2, x_out);
    global_kernel<<<Gg, 128>>>(u, Wg1, bg1, Wg2, bg2, u_out);
}